// round 16
// baseline (speedup 1.0000x reference)
#include <cuda_runtime.h>
#include <cuda_fp16.h>
#include <cstdint>
#include <math.h>

#define Hdim 1024
#define Bdim 256
#define Tdim 64
#define Odim 8192
#define MTOT (Tdim*Bdim)
#define NCTA 128
#define RSTR 144           // row stride bytes for BK=64 tile row (64 half + 16B pad)

typedef __half fp16;

// ---------------- scratch ---------------------------------------------------
__device__ __align__(128) fp16 g_Wih_hi[2u*Hdim*Hdim];
__device__ __align__(128) fp16 g_Wih_lo[2u*Hdim*Hdim];
__device__ __align__(128) fp16 g_Whh_hi[2u*Hdim*Hdim];
__device__ __align__(128) fp16 g_Whh_lo[2u*Hdim*Hdim];
__device__ __align__(128) fp16 g_fcW[(size_t)Odim*Hdim];
__device__ __align__(128) fp16 g_out_hi[(size_t)MTOT*Hdim];
__device__ __align__(128) fp16 g_out_lo[(size_t)MTOT*Hdim];
__device__ __align__(128) fp16 g_h0_hi[2u*Bdim*Hdim];
__device__ __align__(128) fp16 g_h0_lo[2u*Bdim*Hdim];
__device__ __align__(128) fp16 g_x_hi[Bdim*Hdim];
__device__ __align__(128) fp16 g_x_lo[Bdim*Hdim];
__device__ __align__(128) fp16 g_hid_hi[2u*Bdim*Hdim];
__device__ __align__(128) fp16 g_hid_lo[2u*Bdim*Hdim];

__device__ unsigned g_flags[NCTA];   // statically 0; re-zeroed by end-of-run memset

// ---------------- helpers ---------------------------------------------------
__device__ __forceinline__ uint32_t smem_u32(const void* p) {
    uint32_t a;
    asm("{ .reg .u64 t; cvta.to.shared.u64 t, %1; cvt.u32.u64 %0, t; }"
        : "=r"(a) : "l"(p));
    return a;
}

__device__ __forceinline__ unsigned ld_acq(const unsigned* p) {
    unsigned v;
    asm volatile("ld.acquire.gpu.u32 %0, [%1];" : "=r"(v) : "l"(p));
    return v;
}
__device__ __forceinline__ void st_rel(unsigned* p, unsigned v) {
    asm volatile("st.release.gpu.u32 [%0], %1;" :: "l"(p), "r"(v));
}

__device__ __forceinline__ void ldsm4(uint32_t* r, uint32_t addr) {
    asm volatile("ldmatrix.sync.aligned.m8n8.x4.shared.b16 {%0,%1,%2,%3}, [%4];"
                 : "=r"(r[0]), "=r"(r[1]), "=r"(r[2]), "=r"(r[3]) : "r"(addr));
}

__device__ __forceinline__ void hmma(float* c, const uint32_t* a, const uint32_t* b) {
    asm volatile("mma.sync.aligned.m16n8k16.row.col.f32.f16.f16.f32 "
                 "{%0,%1,%2,%3}, {%4,%5,%6,%7}, {%8,%9}, {%0,%1,%2,%3};"
                 : "+f"(c[0]), "+f"(c[1]), "+f"(c[2]), "+f"(c[3])
                 : "r"(a[0]), "r"(a[1]), "r"(a[2]), "r"(a[3]),
                   "r"(b[0]), "r"(b[1]));
}

#define CP_ASYNC16(so, g) \
    asm volatile("cp.async.cg.shared.global [%0], [%1], 16;" :: "r"(so), "l"(g))
#define CP_COMMIT()  asm volatile("cp.async.commit_group;" ::: "memory")
#define CP_WAIT2()   asm volatile("cp.async.wait_group 2;" ::: "memory")
#define CP_WAIT1()   asm volatile("cp.async.wait_group 1;" ::: "memory")
#define CP_WAIT0()   asm volatile("cp.async.wait_group 0;" ::: "memory")

#define BAR_SYNC(id, n)   asm volatile("bar.sync %0, %1;"   :: "r"(id), "r"(n) : "memory")
#define BAR_ARRIVE(id, n) asm volatile("bar.arrive %0, %1;" :: "r"(id), "r"(n) : "memory")

// ---------------- fused prep ------------------------------------------------
#define PREP_R0 (2*Hdim*Hdim/8)
#define PREP_R1 (2*PREP_R0)
#define PREP_R2 (PREP_R1 + Bdim*Hdim/8)
#define PREP_R3 (PREP_R2 + 2*Bdim*Hdim/8)
#define PREP_R4 (PREP_R3 + Odim*Hdim/8)

__global__ void prep_kernel(
    const float4* __restrict__ W_ih, const float4* __restrict__ W_hh,
    const float4* __restrict__ x,    const float4* __restrict__ hidden,
    const float4* __restrict__ fc_W,
    uint4* __restrict__ WihH, uint4* __restrict__ WihL,
    uint4* __restrict__ WhhH, uint4* __restrict__ WhhL,
    uint4* __restrict__ xH,   uint4* __restrict__ xL,
    uint4* __restrict__ hidH, uint4* __restrict__ hidL,
    uint4* __restrict__ fcW)
{
    int i = blockIdx.x * blockDim.x + threadIdx.x;
    if (i >= PREP_R4) return;

    const float4* src;
    uint4 *dh, *dl;
    int j;
    bool do_split = true;
    if (i < PREP_R0)      { j = i;           src = W_ih;   dh = WihH; dl = WihL; }
    else if (i < PREP_R1) { j = i - PREP_R0; src = W_hh;   dh = WhhH; dl = WhhL; }
    else if (i < PREP_R2) { j = i - PREP_R1; src = x;      dh = xH;   dl = xL;   }
    else if (i < PREP_R3) { j = i - PREP_R2; src = hidden; dh = hidH; dl = hidL; }
    else                  { j = i - PREP_R3; src = fc_W;   dh = fcW;  dl = nullptr; do_split = false; }

    float4 a = src[2 * j], b = src[2 * j + 1];
    float v[8] = {a.x, a.y, a.z, a.w, b.x, b.y, b.z, b.w};
    __half h[8], l[8];
#pragma unroll
    for (int k = 0; k < 8; k++) {
        h[k] = __float2half_rn(v[k]);
        l[k] = __float2half_rn(v[k] - __half2float(h[k]));
    }
    uint4 ph;
    ph.x = ((uint32_t)__half_as_ushort(h[1]) << 16) | __half_as_ushort(h[0]);
    ph.y = ((uint32_t)__half_as_ushort(h[3]) << 16) | __half_as_ushort(h[2]);
    ph.z = ((uint32_t)__half_as_ushort(h[5]) << 16) | __half_as_ushort(h[4]);
    ph.w = ((uint32_t)__half_as_ushort(h[7]) << 16) | __half_as_ushort(h[6]);
    dh[j] = ph;
    if (do_split) {
        uint4 pl;
        pl.x = ((uint32_t)__half_as_ushort(l[1]) << 16) | __half_as_ushort(l[0]);
        pl.y = ((uint32_t)__half_as_ushort(l[3]) << 16) | __half_as_ushort(l[2]);
        pl.z = ((uint32_t)__half_as_ushort(l[5]) << 16) | __half_as_ushort(l[4]);
        pl.w = ((uint32_t)__half_as_ushort(l[7]) << 16) | __half_as_ushort(l[6]);
        dl[j] = pl;
    }
}

// ---------------- persistent RNN: warp-specialized halves -------------------
// 128 CTAs, tile BM=64 x BN=32, BK=64.
// Warps 0-3 (group I): dep half inp@Wih, merge, epilogue, flag arrive.
// Warps 4-7 (group H): indep half hprev@Whh (2 phases of slack), smem partial.
// Each group: private 3-stage pipeline; group syncs via named barriers 1/2;
// partial handoff via parity-alternating named barriers 3/4 (arrive/sync).
__global__ void __launch_bounds__(256) persistent_rnn(
    const fp16* __restrict__ xH,   const fp16* __restrict__ xL,
    const fp16* __restrict__ hidH, const fp16* __restrict__ hidL,
    const fp16* __restrict__ WihH, const fp16* __restrict__ WihL,
    const fp16* __restrict__ WhhH, const fp16* __restrict__ WhhL,
    const float* __restrict__ b_ih, const float* __restrict__ b_hh,
    fp16* __restrict__ outH, fp16* __restrict__ outL,
    fp16* __restrict__ h0H,  fp16* __restrict__ h0L)
{
    constexpr int STAGE = 192 * RSTR;            // 27648 B per stage per group
    constexpr int offAl = 64 * RSTR;
    constexpr int offBh = 128 * RSTR;
    constexpr int offBl = 160 * RSTR;
    constexpr int GH_BASE = 3 * STAGE;           // group H pipeline base
    constexpr int PART_BASE = 6 * STAGE;         // fp32 partial, 2 x 64*32
    constexpr int BH = Bdim * Hdim;
    constexpr size_t HH = (size_t)Hdim * Hdim;

    extern __shared__ char sm[];
    const uint32_t smb = smem_u32(sm);
    float* part0 = (float*)(sm + PART_BASE);

    const int tid = threadIdx.x;
    const int wid = tid >> 5, lid = tid & 31;
    const bool isH = (wid >= 4);
    const int gtid = tid & 127;                  // tid within group
    const int wm = wid & 3;                      // warp m-tile within group
    const int bm = (blockIdx.x & 3) * 64;
    const int bn = (blockIdx.x >> 2) * 32;
    const int gbar = isH ? 2 : 1;                // group-private barrier id
    const uint32_t gsb = smb + (isH ? GH_BASE : 0);

    float acc[4][4];                             // NI=4 n-tiles x 4 frags

    // acc += A[64x1024] @ B^T[32x1024]; 16 iters, 3-stage pipeline (group-local)
    auto run_half = [&](const fp16* pAh, const fp16* pAl,
                        const fp16* pBh, const fp16* pBl) {
        auto load_stage = [&](int it) {
            const int k0 = it * 64;
            const uint32_t sb = gsb + (uint32_t)(it % 3) * STAGE;
            // 192 slots x 8 chunks = 1536 transfers / 128 threads = 12 each
#pragma unroll
            for (int rep = 0; rep < 12; rep++) {
                const int idx = rep * 128 + gtid;
                const int slot = idx >> 3, c = idx & 7;
                const uint32_t so = sb + slot * RSTR + c * 16;
                const fp16* g;
                if (slot < 64)       g = pAh + (size_t)(bm + slot) * Hdim + k0 + c * 8;
                else if (slot < 128) g = pAl + (size_t)(bm + slot - 64) * Hdim + k0 + c * 8;
                else if (slot < 160) g = pBh + (size_t)(bn + slot - 128) * Hdim + k0 + c * 8;
                else                 g = pBl + (size_t)(bn + slot - 160) * Hdim + k0 + c * 8;
                CP_ASYNC16(so, g);
            }
        };

        load_stage(0); CP_COMMIT();
        load_stage(1); CP_COMMIT();

#pragma unroll 1
        for (int it = 0; it < 16; ++it) {
            CP_WAIT1();
            BAR_SYNC(gbar, 128);
            if (it + 2 < 16) { load_stage(it + 2); CP_COMMIT(); }
            else { CP_COMMIT(); }

            const uint32_t sb = gsb + (uint32_t)(it % 3) * STAGE;
#pragma unroll
            for (int kk = 0; kk < 4; kk++) {
                uint32_t ah[4], al[4];
                {
                    const int row = wm * 16 + (lid & 15);
                    const int col = kk * 16 + ((lid >> 4) << 3);
                    const uint32_t off = row * RSTR + col * 2;
                    ldsm4(ah, sb + off);
                    ldsm4(al, sb + offAl + off);
                }
                uint32_t bh[4][2], bl[4][2];
                {
                    const int row = (lid & 7) + ((lid & 16) ? 8 : 0);
                    const int col = kk * 16 + ((lid & 8) ? 8 : 0);
                    uint32_t off = row * RSTR + col * 2;
                    uint32_t r[4];
                    ldsm4(r, sb + offBh + off);
                    bh[0][0] = r[0]; bh[0][1] = r[1]; bh[1][0] = r[2]; bh[1][1] = r[3];
                    ldsm4(r, sb + offBl + off);
                    bl[0][0] = r[0]; bl[0][1] = r[1]; bl[1][0] = r[2]; bl[1][1] = r[3];
                    off += 16 * RSTR;
                    ldsm4(r, sb + offBh + off);
                    bh[2][0] = r[0]; bh[2][1] = r[1]; bh[3][0] = r[2]; bh[3][1] = r[3];
                    ldsm4(r, sb + offBl + off);
                    bl[2][0] = r[0]; bl[2][1] = r[1]; bl[3][0] = r[2]; bl[3][1] = r[3];
                }
#pragma unroll
                for (int ni = 0; ni < 4; ni++) hmma(acc[ni], ah, bh[ni]);
#pragma unroll
                for (int ni = 0; ni < 4; ni++) hmma(acc[ni], al, bh[ni]);
#pragma unroll
                for (int ni = 0; ni < 4; ni++) hmma(acc[ni], ah, bl[ni]);
            }
        }
        CP_WAIT0();
        BAR_SYNC(gbar, 128);
    };

    // poll all 128 CTA flags (each group thread owns one flag), group-synced
    auto wait_flags = [&](unsigned tgt) {
        const unsigned* f = &g_flags[gtid];
        for (;;) {
            unsigned v = ld_acq(f);
            if (__all_sync(0xffffffffu, v >= tgt)) break;
            __nanosleep(64);
        }
        BAR_SYNC(gbar, 128);
    };

#pragma unroll 1
    for (int p = 0; p < 2 * Tdim; ++p) {
        const int t = p >> 1, layer = p & 1;

#pragma unroll
        for (int ni = 0; ni < 4; ni++)
#pragma unroll
            for (int q = 0; q < 4; q++) acc[ni][q] = 0.0f;

        if (isH) {
            // -------- group H: indep half (needs phase p-2 => flags >= p-1) --
            const fp16 *Ah, *Al;
            if (layer == 0) {
                Ah = t ? h0H + (size_t)((t - 1) & 1) * BH : hidH;
                Al = t ? h0L + (size_t)((t - 1) & 1) * BH : hidL;
            } else {
                Ah = t ? outH + (size_t)(t - 1) * BH : hidH + BH;
                Al = t ? outL + (size_t)(t - 1) * BH : hidL + BH;
            }
            if (p >= 2) wait_flags((unsigned)(p - 1));   // also releases partial[p&1]

            run_half(Ah, Al, WhhH + layer * HH, WhhL + layer * HH);

            // write fp32 partial to smem slot p&1
            float* part = part0 + (p & 1) * (64 * 32);
#pragma unroll
            for (int ni = 0; ni < 4; ni++) {
                const int r = wm * 16 + (lid >> 2);
                const int col = ni * 8 + (lid & 3) * 2;
#pragma unroll
                for (int h2 = 0; h2 < 2; h2++) {
                    float2 pp;
                    pp.x = acc[ni][2 * h2 + 0];
                    pp.y = acc[ni][2 * h2 + 1];
                    *(float2*)(part + (r + h2 * 8) * 32 + col) = pp;
                }
            }
            __threadfence_block();
            BAR_ARRIVE(3 + (p & 1), 256);
        } else {
            // -------- group I: dep half (needs phase p-1 => flags >= p) ------
            const fp16 *Ah, *Al;
            if (layer == 0) {
                Ah = t ? outH + (size_t)(t - 1) * BH : xH;
                Al = t ? outL + (size_t)(t - 1) * BH : xL;
            } else {
                Ah = h0H + (size_t)(t & 1) * BH;
                Al = h0L + (size_t)(t & 1) * BH;
            }
            if (p >= 1) wait_flags((unsigned)p);

            run_half(Ah, Al, WihH + layer * HH, WihL + layer * HH);

            // wait for group H's partial, then merge + bias + tanh + split
            BAR_SYNC(3 + (p & 1), 256);

            const float* part = part0 + (p & 1) * (64 * 32);
            const float* bi0 = b_ih + layer * Hdim;
            const float* bi1 = b_hh + layer * Hdim;
            fp16* dH = (layer == 0) ? h0H + (size_t)(t & 1) * BH : outH + (size_t)t * BH;
            fp16* dL = (layer == 0) ? h0L + (size_t)(t & 1) * BH : outL + (size_t)t * BH;

#pragma unroll
            for (int ni = 0; ni < 4; ni++) {
                const int r = wm * 16 + (lid >> 2);
                const int col = ni * 8 + (lid & 3) * 2;
                const float bv0 = bi0[bn + col] + bi1[bn + col];
                const float bv1 = bi0[bn + col + 1] + bi1[bn + col + 1];
#pragma unroll
                for (int h2 = 0; h2 < 2; h2++) {
                    const int rr = r + h2 * 8;
                    const float2 pp = *(const float2*)(part + rr * 32 + col);
                    float v0 = tanhf(acc[ni][2 * h2 + 0] + pp.x + bv0);
                    float v1 = tanhf(acc[ni][2 * h2 + 1] + pp.y + bv1);
                    __half h0v = __float2half_rn(v0);
                    __half h1v = __float2half_rn(v1);
                    __half l0v = __float2half_rn(v0 - __half2float(h0v));
                    __half l1v = __float2half_rn(v1 - __half2float(h1v));
                    *(__half2*)(dH + (size_t)(bm + rr) * Hdim + bn + col) =
                        __halves2half2(h0v, h1v);
                    *(__half2*)(dL + (size_t)(bm + rr) * Hdim + bn + col) =
                        __halves2half2(l0v, l1v);
                }
            }

            BAR_SYNC(1, 128);
            if (tid == 0) {
                __threadfence();
                st_rel(&g_flags[blockIdx.x], (unsigned)(p + 1));
            }
        }
    }
    // flags re-zeroed by end-of-run memset (deadlock-free replay)
}

// ---------------- fc GEMM: 1-combo fp16, BM=128 BN=128 BK=64, 3-stage occ 2 -
__global__ void __launch_bounds__(256, 2) fc_gemm(
    const fp16* __restrict__ Ah,
    const fp16* __restrict__ B,
    const float* __restrict__ bias, float* __restrict__ outf)
{
    constexpr int STAGE = 256 * RSTR;      // 36864 B; 3 stages = 110592
    constexpr int offB  = 128 * RSTR;

    extern __shared__ char sm[];
    const uint32_t smb = smem_u32(sm);
    const int tid = threadIdx.x;
    const int wid = tid >> 5, lid = tid & 31;
    const int wm = wid & 3, wn = wid >> 2;
    const int bm = blockIdx.x * 128, bn = blockIdx.y * 128;

    float acc[2][8][4];
#pragma unroll
    for (int mi = 0; mi < 2; mi++)
#pragma unroll
        for (int ni = 0; ni < 8; ni++)
#pragma unroll
            for (int q = 0; q < 4; q++) acc[mi][ni][q] = 0.0f;

    auto load_stage = [&](int it) {
        const int k0 = it * 64;
        const uint32_t sb = smb + (uint32_t)(it % 3) * STAGE;
#pragma unroll
        for (int rep = 0; rep < 8; rep++) {
            const int idx = rep * 256 + tid;
            const int slot = idx >> 3, c = idx & 7;
            const uint32_t so = sb + slot * RSTR + c * 16;
            const fp16* g;
            if (slot < 128)      g = Ah + (size_t)(bm + slot) * Hdim + k0 + c * 8;
            else                 g = B + (size_t)(bn + slot - 128) * Hdim + k0 + c * 8;
            CP_ASYNC16(so, g);
        }
    };

    load_stage(0); CP_COMMIT();
    load_stage(1); CP_COMMIT();

#pragma unroll 1
    for (int it = 0; it < 16; ++it) {
        CP_WAIT1();
        __syncthreads();
        if (it + 2 < 16) { load_stage(it + 2); CP_COMMIT(); }
        else { CP_COMMIT(); }

        const uint32_t sb = smb + (uint32_t)(it % 3) * STAGE;
#pragma unroll
        for (int kk = 0; kk < 4; kk++) {
            uint32_t ah[2][4];
#pragma unroll
            for (int mi = 0; mi < 2; mi++) {
                const int row = wm * 32 + mi * 16 + (lid & 15);
                const int col = kk * 16 + ((lid >> 4) << 3);
                const uint32_t off = row * RSTR + col * 2;
                ldsm4(ah[mi], sb + off);
            }
            uint32_t bh[8][2];
#pragma unroll
            for (int nb = 0; nb < 4; nb++) {
                const int row = wn * 64 + nb * 16 + (lid & 7) + ((lid & 16) ? 8 : 0);
                const int col = kk * 16 + ((lid & 8) ? 8 : 0);
                const uint32_t off = row * RSTR + col * 2;
                uint32_t r[4];
                ldsm4(r, sb + offB + off);
                bh[2 * nb][0] = r[0]; bh[2 * nb][1] = r[1];
                bh[2 * nb + 1][0] = r[2]; bh[2 * nb + 1][1] = r[3];
            }
#pragma unroll
            for (int mi = 0; mi < 2; mi++)
#pragma unroll
                for (int ni = 0; ni < 8; ni++)
                    hmma(acc[mi][ni], ah[mi], bh[ni]);
        }
        __syncthreads();
    }
    CP_WAIT0();

#pragma unroll
    for (int mi = 0; mi < 2; mi++) {
#pragma unroll
        for (int ni = 0; ni < 8; ni++) {
            const int r = bm + wm * 32 + mi * 16 + (lid >> 2);
            const int col = bn + wn * 64 + ni * 8 + (lid & 3) * 2;
            const float bv0 = bias[col], bv1 = bias[col + 1];
#pragma unroll
            for (int h = 0; h < 2; h++) {
                const int rr = r + h * 8;
                float2 p;
                p.x = acc[mi][ni][2 * h + 0] + bv0;
                p.y = acc[mi][ni][2 * h + 1] + bv1;
                *(float2*)(outf + (size_t)rr * Odim + col) = p;
            }
        }
    }
}

// ---------------- host -------------------------------------------------------
extern "C" void kernel_launch(void* const* d_in, const int* in_sizes, int n_in,
                              void* d_out, int out_size)
{
    const float* x      = (const float*)d_in[0];
    const float* hidden = (const float*)d_in[1];
    const float* W_ih   = (const float*)d_in[3];
    const float* W_hh   = (const float*)d_in[4];
    const float* b_ih   = (const float*)d_in[5];
    const float* b_hh   = (const float*)d_in[6];
    const float* fc_W   = (const float*)d_in[7];
    const float* fc_b   = (const float*)d_in[8];
    float* out = (float*)d_out;

    fp16 *Wih_hi, *Wih_lo, *Whh_hi, *Whh_lo, *fcW;
    fp16 *out_hi, *out_lo, *h0_hi, *h0_lo, *x_hi, *x_lo, *hid_hi, *hid_lo;
    unsigned* flags;
    cudaGetSymbolAddress((void**)&Wih_hi, g_Wih_hi);
    cudaGetSymbolAddress((void**)&Wih_lo, g_Wih_lo);
    cudaGetSymbolAddress((void**)&Whh_hi, g_Whh_hi);
    cudaGetSymbolAddress((void**)&Whh_lo, g_Whh_lo);
    cudaGetSymbolAddress((void**)&fcW, g_fcW);
    cudaGetSymbolAddress((void**)&out_hi, g_out_hi);
    cudaGetSymbolAddress((void**)&out_lo, g_out_lo);
    cudaGetSymbolAddress((void**)&h0_hi, g_h0_hi);
    cudaGetSymbolAddress((void**)&h0_lo, g_h0_lo);
    cudaGetSymbolAddress((void**)&x_hi, g_x_hi);
    cudaGetSymbolAddress((void**)&x_lo, g_x_lo);
    cudaGetSymbolAddress((void**)&hid_hi, g_hid_hi);
    cudaGetSymbolAddress((void**)&hid_lo, g_hid_lo);
    cudaGetSymbolAddress((void**)&flags, g_flags);

    prep_kernel<<<(PREP_R4 + 255) / 256, 256>>>(
        (const float4*)W_ih, (const float4*)W_hh,
        (const float4*)x, (const float4*)hidden, (const float4*)fc_W,
        (uint4*)Wih_hi, (uint4*)Wih_lo,
        (uint4*)Whh_hi, (uint4*)Whh_lo,
        (uint4*)x_hi, (uint4*)x_lo,
        (uint4*)hid_hi, (uint4*)hid_lo,
        (uint4*)fcW);

    constexpr int SM_RNN = 6 * 192 * RSTR + 2 * 64 * 32 * 4;   // 165888+16384=182272
    constexpr int SM_FC  = 3 * 256 * RSTR;                     // 110592
    cudaFuncSetAttribute(persistent_rnn,
                         cudaFuncAttributeMaxDynamicSharedMemorySize, SM_RNN);
    cudaFuncSetAttribute(fc_gemm,
                         cudaFuncAttributeMaxDynamicSharedMemorySize, SM_FC);

    persistent_rnn<<<NCTA, 256, SM_RNN>>>(
        x_hi, x_lo, hid_hi, hid_lo,
        Wih_hi, Wih_lo, Whh_hi, Whh_lo,
        b_ih, b_hh,
        out_hi, out_lo, h0_hi, h0_lo);

    const dim3 fc_grid(MTOT / 128, Odim / 128);  // (128, 64)
    fc_gemm<<<fc_grid, 256, SM_FC>>>(
        out_hi, fcW, fc_b, out);

    // reset flags for the next replay (invariant: flags == 0 at kernel entry)
    cudaMemsetAsync(flags, 0, NCTA * sizeof(unsigned), 0);
}

// round 17
// speedup vs baseline: 1.0943x; 1.0943x over previous
#include <cuda_runtime.h>
#include <cuda_fp16.h>
#include <cstdint>
#include <math.h>

#define Hdim 1024
#define Bdim 256
#define Tdim 64
#define Odim 8192
#define MTOT (Tdim*Bdim)
#define NCTA 128
#define RSTR 144           // row stride bytes for BK=64 tile row (64 half + 16B pad)

typedef __half fp16;

// ---------------- scratch ---------------------------------------------------
__device__ __align__(128) fp16 g_Wih_hi[2u*Hdim*Hdim];
__device__ __align__(128) fp16 g_Wih_lo[2u*Hdim*Hdim];
__device__ __align__(128) fp16 g_Whh_hi[2u*Hdim*Hdim];
__device__ __align__(128) fp16 g_Whh_lo[2u*Hdim*Hdim];
__device__ __align__(128) fp16 g_fcW[(size_t)Odim*Hdim];
__device__ __align__(128) fp16 g_out_hi[(size_t)MTOT*Hdim];
__device__ __align__(128) fp16 g_out_lo[(size_t)MTOT*Hdim];
__device__ __align__(128) fp16 g_h0_hi[2u*Bdim*Hdim];
__device__ __align__(128) fp16 g_h0_lo[2u*Bdim*Hdim];
__device__ __align__(128) fp16 g_x_hi[Bdim*Hdim];
__device__ __align__(128) fp16 g_x_lo[Bdim*Hdim];
__device__ __align__(128) fp16 g_hid_hi[2u*Bdim*Hdim];
__device__ __align__(128) fp16 g_hid_lo[2u*Bdim*Hdim];

__device__ unsigned g_flags[NCTA];   // statically 0; re-zeroed by end-of-run memset

// ---------------- helpers ---------------------------------------------------
__device__ __forceinline__ uint32_t smem_u32(const void* p) {
    uint32_t a;
    asm("{ .reg .u64 t; cvta.to.shared.u64 t, %1; cvt.u32.u64 %0, t; }"
        : "=r"(a) : "l"(p));
    return a;
}

__device__ __forceinline__ unsigned ld_acq(const unsigned* p) {
    unsigned v;
    asm volatile("ld.acquire.gpu.u32 %0, [%1];" : "=r"(v) : "l"(p));
    return v;
}
__device__ __forceinline__ void st_rel(unsigned* p, unsigned v) {
    asm volatile("st.release.gpu.u32 [%0], %1;" :: "l"(p), "r"(v));
}

__device__ __forceinline__ void ldsm4(uint32_t* r, uint32_t addr) {
    asm volatile("ldmatrix.sync.aligned.m8n8.x4.shared.b16 {%0,%1,%2,%3}, [%4];"
                 : "=r"(r[0]), "=r"(r[1]), "=r"(r[2]), "=r"(r[3]) : "r"(addr));
}

__device__ __forceinline__ void hmma(float* c, const uint32_t* a, const uint32_t* b) {
    asm volatile("mma.sync.aligned.m16n8k16.row.col.f32.f16.f16.f32 "
                 "{%0,%1,%2,%3}, {%4,%5,%6,%7}, {%8,%9}, {%0,%1,%2,%3};"
                 : "+f"(c[0]), "+f"(c[1]), "+f"(c[2]), "+f"(c[3])
                 : "r"(a[0]), "r"(a[1]), "r"(a[2]), "r"(a[3]),
                   "r"(b[0]), "r"(b[1]));
}

#define CP_ASYNC16(so, g) \
    asm volatile("cp.async.cg.shared.global [%0], [%1], 16;" :: "r"(so), "l"(g))
#define CP_COMMIT()  asm volatile("cp.async.commit_group;" ::: "memory")
#define CP_WAIT2()   asm volatile("cp.async.wait_group 2;" ::: "memory")
#define CP_WAIT1()   asm volatile("cp.async.wait_group 1;" ::: "memory")
#define CP_WAIT0()   asm volatile("cp.async.wait_group 0;" ::: "memory")

// ---------------- fused prep ------------------------------------------------
#define PREP_R0 (2*Hdim*Hdim/8)
#define PREP_R1 (2*PREP_R0)
#define PREP_R2 (PREP_R1 + Bdim*Hdim/8)
#define PREP_R3 (PREP_R2 + 2*Bdim*Hdim/8)
#define PREP_R4 (PREP_R3 + Odim*Hdim/8)

__global__ void prep_kernel(
    const float4* __restrict__ W_ih, const float4* __restrict__ W_hh,
    const float4* __restrict__ x,    const float4* __restrict__ hidden,
    const float4* __restrict__ fc_W,
    uint4* __restrict__ WihH, uint4* __restrict__ WihL,
    uint4* __restrict__ WhhH, uint4* __restrict__ WhhL,
    uint4* __restrict__ xH,   uint4* __restrict__ xL,
    uint4* __restrict__ hidH, uint4* __restrict__ hidL,
    uint4* __restrict__ fcW)
{
    int i = blockIdx.x * blockDim.x + threadIdx.x;
    if (i >= PREP_R4) return;

    const float4* src;
    uint4 *dh, *dl;
    int j;
    bool do_split = true;
    if (i < PREP_R0)      { j = i;           src = W_ih;   dh = WihH; dl = WihL; }
    else if (i < PREP_R1) { j = i - PREP_R0; src = W_hh;   dh = WhhH; dl = WhhL; }
    else if (i < PREP_R2) { j = i - PREP_R1; src = x;      dh = xH;   dl = xL;   }
    else if (i < PREP_R3) { j = i - PREP_R2; src = hidden; dh = hidH; dl = hidL; }
    else                  { j = i - PREP_R3; src = fc_W;   dh = fcW;  dl = nullptr; do_split = false; }

    float4 a = src[2 * j], b = src[2 * j + 1];
    float v[8] = {a.x, a.y, a.z, a.w, b.x, b.y, b.z, b.w};
    __half h[8], l[8];
#pragma unroll
    for (int k = 0; k < 8; k++) {
        h[k] = __float2half_rn(v[k]);
        l[k] = __float2half_rn(v[k] - __half2float(h[k]));
    }
    uint4 ph;
    ph.x = ((uint32_t)__half_as_ushort(h[1]) << 16) | __half_as_ushort(h[0]);
    ph.y = ((uint32_t)__half_as_ushort(h[3]) << 16) | __half_as_ushort(h[2]);
    ph.z = ((uint32_t)__half_as_ushort(h[5]) << 16) | __half_as_ushort(h[4]);
    ph.w = ((uint32_t)__half_as_ushort(h[7]) << 16) | __half_as_ushort(h[6]);
    dh[j] = ph;
    if (do_split) {
        uint4 pl;
        pl.x = ((uint32_t)__half_as_ushort(l[1]) << 16) | __half_as_ushort(l[0]);
        pl.y = ((uint32_t)__half_as_ushort(l[3]) << 16) | __half_as_ushort(l[2]);
        pl.z = ((uint32_t)__half_as_ushort(l[5]) << 16) | __half_as_ushort(l[4]);
        pl.w = ((uint32_t)__half_as_ushort(l[7]) << 16) | __half_as_ushort(l[6]);
        dl[j] = pl;
    }
}

// ---------------- persistent RNN: K-split warp layout ------------------------
// 128 CTAs, tile BM=64 x BN=32, BK=64, 4-stage pipeline.
// 8 warps = 2(m-group of 32 rows) x 4(k-group of 16 cols within BK).
// Warp (gm, gk): MI=2, NI=4 over its K=16 slice; k-partial accumulators are
// reduced ONCE per phase via smem (reusing stage buffers) in the epilogue.
__global__ void __launch_bounds__(256) persistent_rnn(
    const fp16* __restrict__ xH,   const fp16* __restrict__ xL,
    const fp16* __restrict__ hidH, const fp16* __restrict__ hidL,
    const fp16* __restrict__ WihH, const fp16* __restrict__ WihL,
    const fp16* __restrict__ WhhH, const fp16* __restrict__ WhhL,
    const float* __restrict__ b_ih, const float* __restrict__ b_hh,
    fp16* __restrict__ outH, fp16* __restrict__ outL,
    fp16* __restrict__ h0H,  fp16* __restrict__ h0L)
{
    constexpr int STAGE = 192 * RSTR;
    constexpr int offAl = 64 * RSTR;
    constexpr int offBh = 128 * RSTR;
    constexpr int offBl = 160 * RSTR;
    constexpr int BH = Bdim * Hdim;
    constexpr size_t HH = (size_t)Hdim * Hdim;

    extern __shared__ char sm[];
    const uint32_t smb = smem_u32(sm);
    float* red = (float*)sm;                  // reduction scratch (stage area reuse)

    const int tid = threadIdx.x;
    const int wid = tid >> 5, lid = tid & 31;
    const int gm = wid >> 2;                  // m-group 0/1 (32 rows each)
    const int gk = wid & 3;                   // k-group 0..3 (16 cols of BK=64)
    const int bm = (blockIdx.x & 3) * 64;
    const int bn = (blockIdx.x >> 2) * 32;

    float acc[2][4][4];                       // [mi][ni][frag]

    auto run_half = [&](const fp16* pAh, const fp16* pAl,
                        const fp16* pBh, const fp16* pBl) {
        auto load_stage = [&](int it) {
            const int k0 = it * 64;
            const uint32_t sb = smb + (uint32_t)(it & 3) * STAGE;
#pragma unroll
            for (int rep = 0; rep < 6; rep++) {
                const int idx = rep * 256 + tid;
                const int slot = idx >> 3, c = idx & 7;
                const uint32_t so = sb + slot * RSTR + c * 16;
                const fp16* g;
                if (slot < 64)       g = pAh + (size_t)(bm + slot) * Hdim + k0 + c * 8;
                else if (slot < 128) g = pAl + (size_t)(bm + slot - 64) * Hdim + k0 + c * 8;
                else if (slot < 160) g = pBh + (size_t)(bn + slot - 128) * Hdim + k0 + c * 8;
                else                 g = pBl + (size_t)(bn + slot - 160) * Hdim + k0 + c * 8;
                CP_ASYNC16(so, g);
            }
        };

        load_stage(0); CP_COMMIT();
        load_stage(1); CP_COMMIT();
        load_stage(2); CP_COMMIT();

#pragma unroll 1
        for (int it = 0; it < 16; ++it) {
            CP_WAIT2();
            __syncthreads();
            if (it + 3 < 16) { load_stage(it + 3); CP_COMMIT(); }
            else { CP_COMMIT(); }

            const uint32_t sb = smb + (uint32_t)(it & 3) * STAGE;
            // A fragments: rows gm*32 + mi*16, cols gk*16
            uint32_t ah[2][4], al[2][4];
#pragma unroll
            for (int mi = 0; mi < 2; mi++) {
                const int row = gm * 32 + mi * 16 + (lid & 15);
                const int col = gk * 16 + ((lid >> 4) << 3);
                const uint32_t off = row * RSTR + col * 2;
                ldsm4(ah[mi], sb + off);
                ldsm4(al[mi], sb + offAl + off);
            }
            // B fragments: all 32 n-rows, cols gk*16
            uint32_t bh[4][2], bl[4][2];
#pragma unroll
            for (int nb = 0; nb < 2; nb++) {
                const int row = nb * 16 + (lid & 7) + ((lid & 16) ? 8 : 0);
                const int col = gk * 16 + ((lid & 8) ? 8 : 0);
                const uint32_t off = row * RSTR + col * 2;
                uint32_t r[4];
                ldsm4(r, sb + offBh + off);
                bh[2 * nb][0] = r[0]; bh[2 * nb][1] = r[1];
                bh[2 * nb + 1][0] = r[2]; bh[2 * nb + 1][1] = r[3];
                ldsm4(r, sb + offBl + off);
                bl[2 * nb][0] = r[0]; bl[2 * nb][1] = r[1];
                bl[2 * nb + 1][0] = r[2]; bl[2 * nb + 1][1] = r[3];
            }
#pragma unroll
            for (int mi = 0; mi < 2; mi++)
#pragma unroll
                for (int ni = 0; ni < 4; ni++)
                    hmma(acc[mi][ni], ah[mi], bh[ni]);
#pragma unroll
            for (int mi = 0; mi < 2; mi++)
#pragma unroll
                for (int ni = 0; ni < 4; ni++)
                    hmma(acc[mi][ni], al[mi], bh[ni]);
#pragma unroll
            for (int mi = 0; mi < 2; mi++)
#pragma unroll
                for (int ni = 0; ni < 4; ni++)
                    hmma(acc[mi][ni], ah[mi], bl[ni]);
        }
        CP_WAIT0();
        __syncthreads();
    };

#pragma unroll 1
    for (int p = 0; p < 2 * Tdim; ++p) {
        const int t = p >> 1, layer = p & 1;

        const fp16 *Aih, *Ail;
        if (layer == 0) {
            Aih = t ? h0H + (size_t)((t - 1) & 1) * BH : hidH;
            Ail = t ? h0L + (size_t)((t - 1) & 1) * BH : hidL;
        } else {
            Aih = t ? outH + (size_t)(t - 1) * BH : hidH + BH;
            Ail = t ? outL + (size_t)(t - 1) * BH : hidL + BH;
        }
        const fp16 *Adh, *Adl;
        if (layer == 0) {
            Adh = t ? outH + (size_t)(t - 1) * BH : xH;
            Adl = t ? outL + (size_t)(t - 1) * BH : xL;
        } else {
            Adh = h0H + (size_t)(t & 1) * BH;
            Adl = h0L + (size_t)(t & 1) * BH;
        }
        const float* bi0 = b_ih + layer * Hdim;
        const float* bi1 = b_hh + layer * Hdim;
        fp16* dH = (layer == 0) ? h0H + (size_t)(t & 1) * BH : outH + (size_t)t * BH;
        fp16* dL = (layer == 0) ? h0L + (size_t)(t & 1) * BH : outL + (size_t)t * BH;

#pragma unroll
        for (int mi = 0; mi < 2; mi++)
#pragma unroll
            for (int ni = 0; ni < 4; ni++)
#pragma unroll
                for (int q = 0; q < 4; q++) acc[mi][ni][q] = 0.0f;

        // 1) independent half (covered by previous iteration's wait)
        run_half(Aih, Ail, WhhH + layer * HH, WhhL + layer * HH);

        // 2) wait for phase p-1
        {
            const unsigned tgt = (unsigned)p;
            for (;;) {
                unsigned v = ld_acq(&g_flags[tid & (NCTA - 1)]);
                if (__syncthreads_and(v >= tgt)) break;
            }
        }

        // 3) dependent half (accumulates into same k-partial registers)
        run_half(Adh, Adl, WihH + layer * HH, WihL + layer * HH);

        // 4) reduction across k-groups + epilogue
        // store partials: plane layout red[gk*2048 + r*32 + c]
#pragma unroll
        for (int mi = 0; mi < 2; mi++) {
#pragma unroll
            for (int ni = 0; ni < 4; ni++) {
                const int r = gm * 32 + mi * 16 + (lid >> 2);
                const int c = ni * 8 + (lid & 3) * 2;
#pragma unroll
                for (int h2 = 0; h2 < 2; h2++) {
                    float2 pp;
                    pp.x = acc[mi][ni][2 * h2 + 0];
                    pp.y = acc[mi][ni][2 * h2 + 1];
                    *(float2*)&red[gk * 2048 + (r + h2 * 8) * 32 + c] = pp;
                }
            }
        }
        __syncthreads();

        // each thread: 8 consecutive outputs of the 64x32 tile
        {
            const int r = tid >> 2;
            const int c0 = (tid & 3) * 8;
            const float4* r0 = (const float4*)&red[r * 32 + c0];
            const float4* r1 = (const float4*)&red[2048 + r * 32 + c0];
            const float4* r2 = (const float4*)&red[4096 + r * 32 + c0];
            const float4* r3 = (const float4*)&red[6144 + r * 32 + c0];
            float s[8];
#pragma unroll
            for (int q = 0; q < 2; q++) {
                float4 a0 = r0[q], a1 = r1[q], a2 = r2[q], a3 = r3[q];
                s[4 * q + 0] = a0.x + a1.x + a2.x + a3.x;
                s[4 * q + 1] = a0.y + a1.y + a2.y + a3.y;
                s[4 * q + 2] = a0.z + a1.z + a2.z + a3.z;
                s[4 * q + 3] = a0.w + a1.w + a2.w + a3.w;
            }
#pragma unroll
            for (int j = 0; j < 8; j += 2) {
                const int col = bn + c0 + j;
                float v0 = tanhf(s[j]     + bi0[col]     + bi1[col]);
                float v1 = tanhf(s[j + 1] + bi0[col + 1] + bi1[col + 1]);
                __half h0v = __float2half_rn(v0);
                __half h1v = __float2half_rn(v1);
                __half l0v = __float2half_rn(v0 - __half2float(h0v));
                __half l1v = __float2half_rn(v1 - __half2float(h1v));
                *(__half2*)(dH + (size_t)(bm + r) * Hdim + col) = __halves2half2(h0v, h1v);
                *(__half2*)(dL + (size_t)(bm + r) * Hdim + col) = __halves2half2(l0v, l1v);
            }
        }
        __syncthreads();   // protect red (stage area) before next phase's fills

        // 5) arrive
        if (tid == 0) {
            __threadfence();
            st_rel(&g_flags[blockIdx.x], (unsigned)(p + 1));
        }
    }
    // flags re-zeroed by end-of-run memset (deadlock-free replay)
}

// ---------------- fc GEMM: 1-combo fp16, BM=128 BN=128 BK=64, 3-stage occ 2 -
__global__ void __launch_bounds__(256, 2) fc_gemm(
    const fp16* __restrict__ Ah,
    const fp16* __restrict__ B,
    const float* __restrict__ bias, float* __restrict__ outf)
{
    constexpr int STAGE = 256 * RSTR;      // 36864 B; 3 stages = 110592
    constexpr int offB  = 128 * RSTR;

    extern __shared__ char sm[];
    const uint32_t smb = smem_u32(sm);
    const int tid = threadIdx.x;
    const int wid = tid >> 5, lid = tid & 31;
    const int wm = wid & 3, wn = wid >> 2;
    const int bm = blockIdx.x * 128, bn = blockIdx.y * 128;

    float acc[2][8][4];
#pragma unroll
    for (int mi = 0; mi < 2; mi++)
#pragma unroll
        for (int ni = 0; ni < 8; ni++)
#pragma unroll
            for (int q = 0; q < 4; q++) acc[mi][ni][q] = 0.0f;

    auto load_stage = [&](int it) {
        const int k0 = it * 64;
        const uint32_t sb = smb + (uint32_t)(it % 3) * STAGE;
#pragma unroll
        for (int rep = 0; rep < 8; rep++) {
            const int idx = rep * 256 + tid;
            const int slot = idx >> 3, c = idx & 7;
            const uint32_t so = sb + slot * RSTR + c * 16;
            const fp16* g;
            if (slot < 128)      g = Ah + (size_t)(bm + slot) * Hdim + k0 + c * 8;
            else                 g = B + (size_t)(bn + slot - 128) * Hdim + k0 + c * 8;
            CP_ASYNC16(so, g);
        }
    };

    load_stage(0); CP_COMMIT();
    load_stage(1); CP_COMMIT();

#pragma unroll 1
    for (int it = 0; it < 16; ++it) {
        CP_WAIT1();
        __syncthreads();
        if (it + 2 < 16) { load_stage(it + 2); CP_COMMIT(); }
        else { CP_COMMIT(); }

        const uint32_t sb = smb + (uint32_t)(it % 3) * STAGE;
#pragma unroll
        for (int kk = 0; kk < 4; kk++) {
            uint32_t ah[2][4];
#pragma unroll
            for (int mi = 0; mi < 2; mi++) {
                const int row = wm * 32 + mi * 16 + (lid & 15);
                const int col = kk * 16 + ((lid >> 4) << 3);
                const uint32_t off = row * RSTR + col * 2;
                ldsm4(ah[mi], sb + off);
            }
            uint32_t bh[8][2];
#pragma unroll
            for (int nb = 0; nb < 4; nb++) {
                const int row = wn * 64 + nb * 16 + (lid & 7) + ((lid & 16) ? 8 : 0);
                const int col = kk * 16 + ((lid & 8) ? 8 : 0);
                const uint32_t off = row * RSTR + col * 2;
                uint32_t r[4];
                ldsm4(r, sb + offB + off);
                bh[2 * nb][0] = r[0]; bh[2 * nb][1] = r[1];
                bh[2 * nb + 1][0] = r[2]; bh[2 * nb + 1][1] = r[3];
            }
#pragma unroll
            for (int mi = 0; mi < 2; mi++)
#pragma unroll
                for (int ni = 0; ni < 8; ni++)
                    hmma(acc[mi][ni], ah[mi], bh[ni]);
        }
        __syncthreads();
    }
    CP_WAIT0();

#pragma unroll
    for (int mi = 0; mi < 2; mi++) {
#pragma unroll
        for (int ni = 0; ni < 8; ni++) {
            const int r = bm + wm * 32 + mi * 16 + (lid >> 2);
            const int col = bn + wn * 64 + ni * 8 + (lid & 3) * 2;
            const float bv0 = bias[col], bv1 = bias[col + 1];
#pragma unroll
            for (int h = 0; h < 2; h++) {
                const int rr = r + h * 8;
                float2 p;
                p.x = acc[mi][ni][2 * h + 0] + bv0;
                p.y = acc[mi][ni][2 * h + 1] + bv1;
                *(float2*)(outf + (size_t)rr * Odim + col) = p;
            }
        }
    }
}

// ---------------- host -------------------------------------------------------
extern "C" void kernel_launch(void* const* d_in, const int* in_sizes, int n_in,
                              void* d_out, int out_size)
{
    const float* x      = (const float*)d_in[0];
    const float* hidden = (const float*)d_in[1];
    const float* W_ih   = (const float*)d_in[3];
    const float* W_hh   = (const float*)d_in[4];
    const float* b_ih   = (const float*)d_in[5];
    const float* b_hh   = (const float*)d_in[6];
    const float* fc_W   = (const float*)d_in[7];
    const float* fc_b   = (const float*)d_in[8];
    float* out = (float*)d_out;

    fp16 *Wih_hi, *Wih_lo, *Whh_hi, *Whh_lo, *fcW;
    fp16 *out_hi, *out_lo, *h0_hi, *h0_lo, *x_hi, *x_lo, *hid_hi, *hid_lo;
    unsigned* flags;
    cudaGetSymbolAddress((void**)&Wih_hi, g_Wih_hi);
    cudaGetSymbolAddress((void**)&Wih_lo, g_Wih_lo);
    cudaGetSymbolAddress((void**)&Whh_hi, g_Whh_hi);
    cudaGetSymbolAddress((void**)&Whh_lo, g_Whh_lo);
    cudaGetSymbolAddress((void**)&fcW, g_fcW);
    cudaGetSymbolAddress((void**)&out_hi, g_out_hi);
    cudaGetSymbolAddress((void**)&out_lo, g_out_lo);
    cudaGetSymbolAddress((void**)&h0_hi, g_h0_hi);
    cudaGetSymbolAddress((void**)&h0_lo, g_h0_lo);
    cudaGetSymbolAddress((void**)&x_hi, g_x_hi);
    cudaGetSymbolAddress((void**)&x_lo, g_x_lo);
    cudaGetSymbolAddress((void**)&hid_hi, g_hid_hi);
    cudaGetSymbolAddress((void**)&hid_lo, g_hid_lo);
    cudaGetSymbolAddress((void**)&flags, g_flags);

    prep_kernel<<<(PREP_R4 + 255) / 256, 256>>>(
        (const float4*)W_ih, (const float4*)W_hh,
        (const float4*)x, (const float4*)hidden, (const float4*)fc_W,
        (uint4*)Wih_hi, (uint4*)Wih_lo,
        (uint4*)Whh_hi, (uint4*)Whh_lo,
        (uint4*)x_hi, (uint4*)x_lo,
        (uint4*)hid_hi, (uint4*)hid_lo,
        (uint4*)fcW);

    constexpr int SM_RNN = 4 * 192 * RSTR;   // 110592 B (red scratch reuses stages)
    constexpr int SM_FC  = 3 * 256 * RSTR;   // 110592 B
    cudaFuncSetAttribute(persistent_rnn,
                         cudaFuncAttributeMaxDynamicSharedMemorySize, SM_RNN);
    cudaFuncSetAttribute(fc_gemm,
                         cudaFuncAttributeMaxDynamicSharedMemorySize, SM_FC);

    persistent_rnn<<<NCTA, 256, SM_RNN>>>(
        x_hi, x_lo, hid_hi, hid_lo,
        Wih_hi, Wih_lo, Whh_hi, Whh_lo,
        b_ih, b_hh,
        out_hi, out_lo, h0_hi, h0_lo);

    const dim3 fc_grid(MTOT / 128, Odim / 128);  // (128, 64)
    fc_gemm<<<fc_grid, 256, SM_FC>>>(
        out_hi, fcW, fc_b, out);

    // reset flags for the next replay (invariant: flags == 0 at kernel entry)
    cudaMemsetAsync(flags, 0, NCTA * sizeof(unsigned), 0);
}